// round 5
// baseline (speedup 1.0000x reference)
#include <cuda_runtime.h>
#include <cuda_bf16.h>
#include <cstdint>

// ---------------------------------------------------------------------------
// Problem constants
// ---------------------------------------------------------------------------
#define BB 4
#define TT 64
#define LL 128
#define DD 768
#define HH 12
#define DH 64
#define MROWS (BB * TT * LL)     // 32768

// ---------------------------------------------------------------------------
// Device scratch (allocation-free per harness rules)
// ---------------------------------------------------------------------------
__device__ __align__(16) __nv_bfloat16 g_Xhi[MROWS * DD];
__device__ __align__(16) __nv_bfloat16 g_Xlo[MROWS * DD];
__device__ __align__(16) __nv_bfloat16 g_Wqhi[DD * DD];
__device__ __align__(16) __nv_bfloat16 g_Wqlo[DD * DD];
__device__ __align__(16) __nv_bfloat16 g_Qhi[MROWS * DD];
__device__ __align__(16) __nv_bfloat16 g_Qlo[MROWS * DD];
// K split:  [B][H][u][d],  V transposed split: [B][H][e][u]
__device__ __align__(16) __nv_bfloat16 g_Khi[BB * HH * DH * DH];
__device__ __align__(16) __nv_bfloat16 g_Klo[BB * HH * DH * DH];
__device__ __align__(16) __nv_bfloat16 g_Vthi[BB * HH * DH * DH];
__device__ __align__(16) __nv_bfloat16 g_Vtlo[BB * HH * DH * DH];

// ---------------------------------------------------------------------------
// Helpers (sm_80-era ISA only: ldmatrix / mma.sync / cp.async)
// ---------------------------------------------------------------------------
__device__ __forceinline__ uint32_t smem_u32(const void* p) {
    uint32_t a;
    asm("{ .reg .u64 t; cvta.to.shared.u64 t, %1; cvt.u32.u64 %0, t; }" : "=r"(a) : "l"(p));
    return a;
}
#define SWZ(off) ((off) ^ (((off) >> 3) & 0x70))

__device__ __forceinline__ void ldsm4(uint32_t* r, uint32_t a) {
    asm volatile("ldmatrix.sync.aligned.m8n8.x4.shared.b16 {%0,%1,%2,%3}, [%4];"
                 : "=r"(r[0]), "=r"(r[1]), "=r"(r[2]), "=r"(r[3]) : "r"(a));
}

// D = A(16x16 bf16, row) * B(16x8 bf16, col) + D, fp32 accum
__device__ __forceinline__ void mma16816(float* c, const uint32_t* a, const uint32_t* b) {
    asm volatile(
        "mma.sync.aligned.m16n8k16.row.col.f32.bf16.bf16.f32 "
        "{%0,%1,%2,%3}, {%4,%5,%6,%7}, {%8,%9}, {%0,%1,%2,%3};"
        : "+f"(c[0]), "+f"(c[1]), "+f"(c[2]), "+f"(c[3])
        : "r"(a[0]), "r"(a[1]), "r"(a[2]), "r"(a[3]), "r"(b[0]), "r"(b[1]));
}

__device__ __forceinline__ void cp_async16(uint32_t saddr, const void* gptr) {
    asm volatile("cp.async.cg.shared.global [%0], [%1], 16;" :: "r"(saddr), "l"(gptr));
}
#define CP_COMMIT() asm volatile("cp.async.commit_group;" ::: "memory")
#define CP_WAIT0()  asm volatile("cp.async.wait_group 0;" ::: "memory")
#define CP_WAIT1()  asm volatile("cp.async.wait_group 1;" ::: "memory")

__device__ __forceinline__ uint32_t pack_bf16(__nv_bfloat16 a, __nv_bfloat16 b) {
    __nv_bfloat162 p; p.x = a; p.y = b;
    return *reinterpret_cast<uint32_t*>(&p);
}
__device__ __forceinline__ void split32(float v, __nv_bfloat16& h, __nv_bfloat16& l) {
    h = __float2bfloat16_rn(v);
    l = __float2bfloat16_rn(v - __bfloat162float(h));
}

// ---------------------------------------------------------------------------
// Kernel 0a/0b: fp32 -> bf16 hi/lo split
// ---------------------------------------------------------------------------
__global__ __launch_bounds__(256) void convert_X_kernel(const float4* __restrict__ src)
{
    int i = blockIdx.x * blockDim.x + threadIdx.x;
    const int n4 = MROWS * DD / 4;
    if (i >= n4) return;
    float4 v = src[i];
    __nv_bfloat16 h0, l0, h1, l1, h2, l2, h3, l3;
    split32(v.x, h0, l0); split32(v.y, h1, l1);
    split32(v.z, h2, l2); split32(v.w, h3, l3);
    *reinterpret_cast<uint2*>(g_Xhi + (size_t)i * 4) =
        make_uint2(pack_bf16(h0, h1), pack_bf16(h2, h3));
    *reinterpret_cast<uint2*>(g_Xlo + (size_t)i * 4) =
        make_uint2(pack_bf16(l0, l1), pack_bf16(l2, l3));
}

__global__ __launch_bounds__(256) void convert_W_kernel(const float4* __restrict__ src)
{
    int i = blockIdx.x * blockDim.x + threadIdx.x;
    const int n4 = DD * DD / 4;
    if (i >= n4) return;
    float4 v = src[i];
    __nv_bfloat16 h0, l0, h1, l1, h2, l2, h3, l3;
    split32(v.x, h0, l0); split32(v.y, h1, l1);
    split32(v.z, h2, l2); split32(v.w, h3, l3);
    *reinterpret_cast<uint2*>(g_Wqhi + (size_t)i * 4) =
        make_uint2(pack_bf16(h0, h1), pack_bf16(h2, h3));
    *reinterpret_cast<uint2*>(g_Wqlo + (size_t)i * 4) =
        make_uint2(pack_bf16(l0, l1), pack_bf16(l2, l3));
}

// ---------------------------------------------------------------------------
// Kernel 1: K/V projections fp32 SIMT; epilogue writes split K / V^T tiles
// ---------------------------------------------------------------------------
__global__ __launch_bounds__(256) void kv_proj_kernel(
    const float* __restrict__ E,
    const float* __restrict__ Wk,
    const float* __restrict__ Wv)
{
    const int isV = blockIdx.z;
    const float* W = isV ? Wv : Wk;
    const int mt = blockIdx.x, nt = blockIdx.y;

    __shared__ float Es[32][17];
    __shared__ float Ws[32][132];

    const int tid = threadIdx.x;
    const int ty = tid >> 4, tx = tid & 15;

    float acc[8];
#pragma unroll
    for (int j = 0; j < 8; j++) acc[j] = 0.f;

    for (int k0 = 0; k0 < DD; k0 += 32) {
        if (tid < 128) {
            int r = tid >> 3, c4 = tid & 7;
            float4 v = *(const float4*)&E[(size_t)(mt * 16 + r) * DD + k0 + c4 * 4];
            Es[c4 * 4 + 0][r] = v.x; Es[c4 * 4 + 1][r] = v.y;
            Es[c4 * 4 + 2][r] = v.z; Es[c4 * 4 + 3][r] = v.w;
        }
#pragma unroll
        for (int it = 0; it < 4; it++) {
            int idx = tid + it * 256;
            int r = idx >> 3, c4 = idx & 7;
            float4 v = *(const float4*)&W[(size_t)(nt * 128 + r) * DD + k0 + c4 * 4];
            Ws[c4 * 4 + 0][r] = v.x; Ws[c4 * 4 + 1][r] = v.y;
            Ws[c4 * 4 + 2][r] = v.z; Ws[c4 * 4 + 3][r] = v.w;
        }
        __syncthreads();
#pragma unroll
        for (int kk = 0; kk < 32; kk++) {
            float e = Es[kk][ty];
            float w[8];
            *(float4*)&w[0] = *(const float4*)&Ws[kk][tx * 8];
            *(float4*)&w[4] = *(const float4*)&Ws[kk][tx * 8 + 4];
#pragma unroll
            for (int j = 0; j < 8; j++) acc[j] = fmaf(e, w[j], acc[j]);
        }
        __syncthreads();
    }

    const int r = mt * 16 + ty;
    const int b = r >> 6, u = r & 63;
    const int c0 = nt * 128 + tx * 8;
    const int h = c0 >> 6, d0 = c0 & 63;
    const int tilebase = ((b * HH + h) * DH) * DH;
#pragma unroll
    for (int j = 0; j < 8; j++) {
        __nv_bfloat16 hi, lo;
        split32(acc[j], hi, lo);
        if (!isV) {
            int idx = tilebase + u * DH + (d0 + j);
            g_Khi[idx] = hi; g_Klo[idx] = lo;
        } else {
            int idx = tilebase + (d0 + j) * DH + u;
            g_Vthi[idx] = hi; g_Vtlo[idx] = lo;
        }
    }
}

// ---------------------------------------------------------------------------
// Kernel 2: Q = X @ Wq^T via mma.sync bf16 hi/lo 3-pass.
// M=32768, N=768, K=768. CTA 128x128, K-chunk 64, double-buffered cp.async.
// 512 threads = 16 warps as 8(M) x 2(N); warp tile 16x64.
// smem stage: Ahi|Alo|Bhi|Blo, each [128][64] bf16, SW128 rows of 128B.
// ---------------------------------------------------------------------------
#define QG_TILE  16384
#define QG_STAGE (4 * QG_TILE)    // 64 KB
#define QG_SMEM  (2 * QG_STAGE)   // 128 KB

__device__ __forceinline__ void qg_load(
    int s, int tid, uint32_t base,
    const __nv_bfloat16* Ah, const __nv_bfloat16* Al,
    const __nv_bfloat16* Bh, const __nv_bfloat16* Bl)
{
    const int k0 = s * 64;
    const uint32_t buf = base + (s & 1) * QG_STAGE;
#pragma unroll
    for (int i = 0; i < 2; i++) {
        int idx = tid + i * 512;          // 1024 16B units: 128 rows x 8
        int r = idx >> 3, c = idx & 7;
        uint32_t sw = SWZ(r * 128 + c * 16);
        size_t g = (size_t)r * DD + k0 + c * 8;
        cp_async16(buf + sw,                Ah + g);
        cp_async16(buf + QG_TILE + sw,      Al + g);
        cp_async16(buf + 2 * QG_TILE + sw,  Bh + g);
        cp_async16(buf + 3 * QG_TILE + sw,  Bl + g);
    }
    CP_COMMIT();
}

__global__ __launch_bounds__(512) void q_gemm_kernel()
{
    extern __shared__ char sm[];
    const uint32_t base = smem_u32(sm);
    const int tid = threadIdx.x, lane = tid & 31, wid = tid >> 5;
    const int wm = wid & 7, wn = wid >> 3;        // 8(M) x 2(N)
    const int nt_b = blockIdx.x, mt_b = blockIdx.y;
    const size_t mrow0 = (size_t)mt_b * 128;
    const int n0 = nt_b * 128;

    const __nv_bfloat16* Ah = g_Xhi  + mrow0 * DD;
    const __nv_bfloat16* Al = g_Xlo  + mrow0 * DD;
    const __nv_bfloat16* Bh = g_Wqhi + (size_t)n0 * DD;
    const __nv_bfloat16* Bl = g_Wqlo + (size_t)n0 * DD;

    float acc[8][4];
#pragma unroll
    for (int nt = 0; nt < 8; nt++)
#pragma unroll
        for (int j = 0; j < 4; j++) acc[nt][j] = 0.f;

    qg_load(0, tid, base, Ah, Al, Bh, Bl);
    qg_load(1, tid, base, Ah, Al, Bh, Bl);

    const int li = lane & 7, mi = lane >> 3;
    // ldmatrix lane-address components (PTX m16n8k16 fragment layouts):
    const int a_row = li + (mi & 1) * 8;          // + R0
    const int a_cb  = (mi >> 1) * 16;             // + k0*2
    const int b_row = li + (mi >> 1) * 8;         // + N0
    const int b_cb  = (mi & 1) * 16;              // + k0*2

    for (int s = 0; s < 12; s++) {
        if (s == 11) CP_WAIT0(); else CP_WAIT1();
        __syncthreads();
        const uint32_t bA  = base + (s & 1) * QG_STAGE;
        const uint32_t bAl = bA + QG_TILE;
        const uint32_t bB  = bA + 2 * QG_TILE;
        const uint32_t bBl = bA + 3 * QG_TILE;

#pragma unroll
        for (int ks = 0; ks < 4; ks++) {
            const int kb = ks * 32;   // byte offset of k0 in 128B row
            uint32_t ah[4], al2[4];
            {
                uint32_t off = SWZ((wm * 16 + a_row) * 128 + kb + a_cb);
                ldsm4(ah,  bA  + off);
                ldsm4(al2, bAl + off);
            }
            uint32_t bh[8][2], bl2[8][2];
#pragma unroll
            for (int bt = 0; bt < 4; bt++) {
                uint32_t off = SWZ((wn * 64 + bt * 16 + b_row) * 128 + kb + b_cb);
                uint32_t t4[4];
                ldsm4(t4, bB + off);
                bh[2 * bt][0] = t4[0]; bh[2 * bt][1] = t4[1];
                bh[2 * bt + 1][0] = t4[2]; bh[2 * bt + 1][1] = t4[3];
                ldsm4(t4, bBl + off);
                bl2[2 * bt][0] = t4[0]; bl2[2 * bt][1] = t4[1];
                bl2[2 * bt + 1][0] = t4[2]; bl2[2 * bt + 1][1] = t4[3];
            }
#pragma unroll
            for (int nt = 0; nt < 8; nt++) {
                mma16816(acc[nt], ah,  bh[nt]);
                mma16816(acc[nt], ah,  bl2[nt]);
                mma16816(acc[nt], al2, bh[nt]);
            }
        }
        __syncthreads();
        if (s + 2 < 12) qg_load(s + 2, tid, base, Ah, Al, Bh, Bl);
    }

    // epilogue: acc -> bf16 hi/lo -> g_Qhi/g_Qlo
    const int q2 = 2 * (lane & 3);
    const int r0 = wm * 16 + (lane >> 2);
#pragma unroll
    for (int nt = 0; nt < 8; nt++) {
        const int col = n0 + wn * 64 + nt * 8 + q2;
        __nv_bfloat16 h0, l0, h1, l1, h2, l2, h3, l3;
        split32(acc[nt][0], h0, l0);
        split32(acc[nt][1], h1, l1);
        split32(acc[nt][2], h2, l2);
        split32(acc[nt][3], h3, l3);
        *reinterpret_cast<uint32_t*>(g_Qhi + (mrow0 + r0)     * DD + col) = pack_bf16(h0, h1);
        *reinterpret_cast<uint32_t*>(g_Qlo + (mrow0 + r0)     * DD + col) = pack_bf16(l0, l1);
        *reinterpret_cast<uint32_t*>(g_Qhi + (mrow0 + r0 + 8) * DD + col) = pack_bf16(h2, h3);
        *reinterpret_cast<uint32_t*>(g_Qlo + (mrow0 + r0 + 8) * DD + col) = pack_bf16(l2, l3);
    }
}

// ---------------------------------------------------------------------------
// Kernel 3: attention per (t, h, b). 256 threads = 8 warps, warp = 16 rows.
//   S = Q @ K^T (mma), mask+split in registers, A = S @ V (mma), out = X + A.
// smem: Qhi 16K | Qlo 16K | Khi 8K | Klo 8K | Vthi 8K | Vtlo 8K | spk 256B
// ---------------------------------------------------------------------------
#define AT_QHI   0
#define AT_QLO   16384
#define AT_KHI   32768
#define AT_KLO   40960
#define AT_VHI   49152
#define AT_VLO   57344
#define AT_SPK   65536
#define AT_SMEM  (AT_SPK + 256)

__global__ __launch_bounds__(256) void attn_kernel(
    const float* __restrict__ X,
    const int*   __restrict__ spk,
    float*       __restrict__ Out)
{
    extern __shared__ char sm[];
    const uint32_t base = smem_u32(sm);
    const int tid = threadIdx.x, lane = tid & 31, wid = tid >> 5;
    const int t = blockIdx.x, h = blockIdx.y, b = blockIdx.z;

    int* spk_s = reinterpret_cast<int*>(sm + AT_SPK);
    if (tid < TT) spk_s[tid] = spk[b * TT + tid];

    const size_t qbase = ((size_t)(b * TT + t) * LL) * DD + h * DH;
    const int kvbase = ((b * HH + h) * DH) * DH;

#pragma unroll
    for (int i = 0; i < 4; i++) {             // Q hi/lo: 128 rows x 8 16B-units
        int idx = tid + i * 256;
        int r = idx >> 3, c = idx & 7;
        uint32_t sw = SWZ(r * 128 + c * 16);
        size_t g = qbase + (size_t)r * DD + c * 8;
        cp_async16(base + AT_QHI + sw, g_Qhi + g);
        cp_async16(base + AT_QLO + sw, g_Qlo + g);
    }
#pragma unroll
    for (int i = 0; i < 2; i++) {             // K, Vt hi/lo: 64 rows x 8 units
        int idx = tid + i * 256;
        int r = idx >> 3, c = idx & 7;
        uint32_t sw = SWZ(r * 128 + c * 16);
        int g = kvbase + r * DH + c * 8;
        cp_async16(base + AT_KHI + sw, g_Khi + g);
        cp_async16(base + AT_KLO + sw, g_Klo + g);
        cp_async16(base + AT_VHI + sw, g_Vthi + g);
        cp_async16(base + AT_VLO + sw, g_Vtlo + g);
    }
    CP_COMMIT();
    CP_WAIT0();
    __syncthreads();

    const int spk_t = spk_s[t];
    const int li = lane & 7, mi = lane >> 3;
    const int a_row = li + (mi & 1) * 8;
    const int a_cb  = (mi >> 1) * 16;
    const int b_row = li + (mi >> 1) * 8;
    const int b_cb  = (mi & 1) * 16;
    const int q2 = 2 * (lane & 3);

    // ---- MMA1: S = Q @ K^T ----  (warp rows wid*16..+16)
    float acc[8][4];
#pragma unroll
    for (int nt = 0; nt < 8; nt++)
#pragma unroll
        for (int j = 0; j < 4; j++) acc[nt][j] = 0.f;

#pragma unroll
    for (int ks = 0; ks < 4; ks++) {
        const int kb = ks * 32;
        uint32_t qh[4], ql[4];
        {
            uint32_t off = SWZ((wid * 16 + a_row) * 128 + kb + a_cb);
            ldsm4(qh, base + AT_QHI + off);
            ldsm4(ql, base + AT_QLO + off);
        }
        uint32_t kh[8][2], kl[8][2];
#pragma unroll
        for (int bt = 0; bt < 4; bt++) {
            uint32_t off = SWZ((bt * 16 + b_row) * 128 + kb + b_cb);
            uint32_t t4[4];
            ldsm4(t4, base + AT_KHI + off);
            kh[2 * bt][0] = t4[0]; kh[2 * bt][1] = t4[1];
            kh[2 * bt + 1][0] = t4[2]; kh[2 * bt + 1][1] = t4[3];
            ldsm4(t4, base + AT_KLO + off);
            kl[2 * bt][0] = t4[0]; kl[2 * bt][1] = t4[1];
            kl[2 * bt + 1][0] = t4[2]; kl[2 * bt + 1][1] = t4[3];
        }
#pragma unroll
        for (int nt = 0; nt < 8; nt++) {
            mma16816(acc[nt], qh, kh[nt]);
            mma16816(acc[nt], qh, kl[nt]);
            mma16816(acc[nt], ql, kh[nt]);
        }
    }

    // ---- mask + hi/lo split in registers ----
    // acc[nt] cols (u0,u1) map to A-frag regs of MMA2: sh[nt/2][(nt&1)*2+{0,1}]
    uint32_t sh[4][4], sl[4][4];
#pragma unroll
    for (int nt = 0; nt < 8; nt++) {
        const int u0 = nt * 8 + q2, u1 = u0 + 1;
        const bool m0 = (u0 <= t) && (spk_s[u0] == spk_t);
        const bool m1 = (u1 <= t) && (spk_s[u1] == spk_t);
        float c0 = m0 ? acc[nt][0] : 0.f;
        float c1 = m1 ? acc[nt][1] : 0.f;
        float c2 = m0 ? acc[nt][2] : 0.f;
        float c3 = m1 ? acc[nt][3] : 0.f;
        __nv_bfloat16 h0, l0, h1, l1, h2, l2, h3, l3;
        split32(c0, h0, l0); split32(c1, h1, l1);
        split32(c2, h2, l2); split32(c3, h3, l3);
        sh[nt >> 1][(nt & 1) * 2 + 0] = pack_bf16(h0, h1);
        sl[nt >> 1][(nt & 1) * 2 + 0] = pack_bf16(l0, l1);
        sh[nt >> 1][(nt & 1) * 2 + 1] = pack_bf16(h2, h3);
        sl[nt >> 1][(nt & 1) * 2 + 1] = pack_bf16(l2, l3);
    }

    // ---- MMA2: A = S @ V  (B operand = Vt[e][u], K = u) ----
    float acc2[8][4];
#pragma unroll
    for (int et = 0; et < 8; et++)
#pragma unroll
        for (int j = 0; j < 4; j++) acc2[et][j] = 0.f;

#pragma unroll
    for (int ks = 0; ks < 4; ks++) {
        const int kb = ks * 32;
        uint32_t vh[8][2], vl[8][2];
#pragma unroll
        for (int bt = 0; bt < 4; bt++) {
            uint32_t off = SWZ((bt * 16 + b_row) * 128 + kb + b_cb);
            uint32_t t4[4];
            ldsm4(t4, base + AT_VHI + off);
            vh[2 * bt][0] = t4[0]; vh[2 * bt][1] = t4[1];
            vh[2 * bt + 1][0] = t4[2]; vh[2 * bt + 1][1] = t4[3];
            ldsm4(t4, base + AT_VLO + off);
            vl[2 * bt][0] = t4[0]; vl[2 * bt][1] = t4[1];
            vl[2 * bt + 1][0] = t4[2]; vl[2 * bt + 1][1] = t4[3];
        }
#pragma unroll
        for (int et = 0; et < 8; et++) {
            mma16816(acc2[et], sh[ks], vh[et]);
            mma16816(acc2[et], sh[ks], vl[et]);
            mma16816(acc2[et], sl[ks], vh[et]);
        }
    }

    // ---- epilogue: out = X + A ----
    const int r0 = wid * 16 + (lane >> 2);
#pragma unroll
    for (int et = 0; et < 8; et++) {
        const int co = et * 8 + q2;
        {
            const size_t g = qbase + (size_t)r0 * DD + co;
            float2 x = *reinterpret_cast<const float2*>(X + g);
            float2 o = make_float2(x.x + acc2[et][0], x.y + acc2[et][1]);
            *reinterpret_cast<float2*>(Out + g) = o;
        }
        {
            const size_t g = qbase + (size_t)(r0 + 8) * DD + co;
            float2 x = *reinterpret_cast<const float2*>(X + g);
            float2 o = make_float2(x.x + acc2[et][2], x.y + acc2[et][3]);
            *reinterpret_cast<float2*>(Out + g) = o;
        }
    }
}

// ---------------------------------------------------------------------------
// kernel_launch: inputs: 0 input_ids (unused), 1 speaker_ids,
// 2 token_embeddings, 3 edu_embeddings, 4 Wk, 5 Wv, 6 Wq. Output fp32.
// ---------------------------------------------------------------------------
extern "C" void kernel_launch(void* const* d_in, const int* in_sizes, int n_in,
                              void* d_out, int out_size)
{
    (void)in_sizes; (void)n_in; (void)out_size;
    const int*   spk = (const int*)d_in[1];
    const float* X   = (const float*)d_in[2];
    const float* E   = (const float*)d_in[3];
    const float* Wk  = (const float*)d_in[4];
    const float* Wv  = (const float*)d_in[5];
    const float* Wq  = (const float*)d_in[6];
    float* out = (float*)d_out;

    const int nx4 = MROWS * DD / 4;
    const int nw4 = DD * DD / 4;
    convert_X_kernel<<<(nx4 + 255) / 256, 256>>>((const float4*)X);
    convert_W_kernel<<<(nw4 + 255) / 256, 256>>>((const float4*)Wq);

    kv_proj_kernel<<<dim3(16, 6, 2), 256>>>(E, Wk, Wv);

    cudaFuncSetAttribute(q_gemm_kernel,
                         cudaFuncAttributeMaxDynamicSharedMemorySize, QG_SMEM);
    cudaFuncSetAttribute(attn_kernel,
                         cudaFuncAttributeMaxDynamicSharedMemorySize, AT_SMEM);

    q_gemm_kernel<<<dim3(6, 256), 512, QG_SMEM>>>();
    attn_kernel<<<dim3(TT, HH, BB), 256, AT_SMEM>>>(X, spk, out);
}